// round 2
// baseline (speedup 1.0000x reference)
#include <cuda_runtime.h>
#include <math.h>

#define NXY   384
#define NROWS 768
#define DATA  4096
#define DM    128
#define EPS   1e-5f
#define KSPL  32
#define KCH   128   // DATA / KSPL
#define GBM   128
#define GBK   16

// ---------------- device scratch ----------------
__device__ float g_Wg[DATA * DM];          // gamma-scaled W transposed: [k][m]
__device__ float g_C1[DM], g_C2[DM];
__device__ float g_mu[NROWS], g_rstd[NROWS];
__device__ float g_part[KSPL * NROWS * DM];
__device__ float g_exy[NROWS * DM];        // ex rows 0..383, ey rows 384..767
__device__ float g_Mx[NXY * NXY], g_Gx[NXY * NXY];
__device__ float g_My[NXY * NXY], g_Gy[NXY * NXY];
__device__ float g_Gwt[NXY * NXY];         // [n][j] (ex_j*wxy)·ey_n
__device__ float g_Gt[NXY * NXY];          // [n][j] ex_j·ey_n
__device__ float g_Apart[NXY * NXY];
__device__ float g_colsum[NXY];
__device__ float g_Araw[NXY];
__device__ float g_arow[NXY];
__device__ float g_zA[DM], g_zB[DM];
__device__ unsigned g_mxbits[3];

// monotone float<->uint ordering map (for atomicMax on floats)
__device__ __forceinline__ unsigned fOrd(float f) {
    unsigned u = __float_as_uint(f);
    return (u & 0x80000000u) ? ~u : (u | 0x80000000u);
}
__device__ __forceinline__ float fUnord(unsigned u) {
    return __uint_as_float((u & 0x80000000u) ? (u & 0x7FFFFFFFu) : ~u);
}

// ---------------- init ----------------
__global__ void k_init() {
    if (threadIdx.x == 0) {
        g_mxbits[0] = fOrd(-3.4e38f);
        g_mxbits[1] = fOrd(0.0f);     // cross-stage UB clamp at 0
        g_mxbits[2] = fOrd(-3.4e38f);
    }
}

// ---------------- W prep: Wg[k][m] = gamma[k] * W[m][k] ----------------
__global__ void __launch_bounds__(1024) k_prepW(const float* __restrict__ W,
                                                const float* __restrict__ gamma) {
    __shared__ float tile[32][33];
    int k0 = blockIdx.x * 32, n0 = blockIdx.y * 32;
    tile[threadIdx.y][threadIdx.x] = W[(size_t)(n0 + threadIdx.y) * DATA + k0 + threadIdx.x];
    __syncthreads();
    int k = k0 + threadIdx.y, n = n0 + threadIdx.x;
    g_Wg[(size_t)k * DM + n] = gamma[k] * tile[threadIdx.x][threadIdx.y];
}

// ---------------- C1[m] = sum gamma*W[m], C2[m] = sum beta*W[m] ----------------
__global__ void __launch_bounds__(256) k_c12(const float* __restrict__ W,
                                             const float* __restrict__ gamma,
                                             const float* __restrict__ beta) {
    int m = blockIdx.x, t = threadIdx.x;
    float c1 = 0.f, c2 = 0.f;
    for (int d = t; d < DATA; d += 256) {
        float wv = W[(size_t)m * DATA + d];
        c1 += gamma[d] * wv;
        c2 += beta[d] * wv;
    }
    __shared__ float r1[256], r2[256];
    r1[t] = c1; r2[t] = c2; __syncthreads();
    for (int off = 128; off; off >>= 1) {
        if (t < off) { r1[t] += r1[t + off]; r2[t] += r2[t + off]; }
        __syncthreads();
    }
    if (t == 0) { g_C1[m] = r1[0]; g_C2[m] = r2[0]; }
}

// ---------------- per-row mean / rstd ----------------
__global__ void __launch_bounds__(256) k_rowstats(const float* __restrict__ x,
                                                  const float* __restrict__ y) {
    int r = blockIdx.x, t = threadIdx.x;
    const float* p = (r < NXY) ? (x + (size_t)r * DATA) : (y + (size_t)(r - NXY) * DATA);
    float s = 0.f, q = 0.f;
    for (int d = t * 4; d < DATA; d += 1024) {
        float4 v = *(const float4*)(p + d);
        s += v.x + v.y + v.z + v.w;
        q += v.x * v.x + v.y * v.y + v.z * v.z + v.w * v.w;
    }
    __shared__ float rs[256], rq[256];
    rs[t] = s; rq[t] = q; __syncthreads();
    for (int off = 128; off; off >>= 1) {
        if (t < off) { rs[t] += rs[t + off]; rq[t] += rq[t + off]; }
        __syncthreads();
    }
    if (t == 0) {
        float mu = rs[0] * (1.f / DATA);
        float var = rq[0] * (1.f / DATA) - mu * mu;
        g_mu[r] = mu;
        g_rstd[r] = rsqrtf(var + EPS);
    }
}

// ---------------- main GEMM: [768 x 4096] @ Wg[4096 x 128], split-K ----------------
__global__ void __launch_bounds__(256) k_gemm(const float* __restrict__ x,
                                              const float* __restrict__ y) {
    __shared__ float As[GBM][GBK + 1];
    __shared__ float Bs[GBK][DM];
    int t = threadIdx.x, tx = t & 15, ty = t >> 4;
    int r0 = blockIdx.x * GBM;
    int ks = blockIdx.z;
    const float* Ab = (r0 < NXY) ? (x + (size_t)r0 * DATA)
                                 : (y + (size_t)(r0 - NXY) * DATA);
    float acc[8][8];
#pragma unroll
    for (int i = 0; i < 8; i++)
#pragma unroll
        for (int j = 0; j < 8; j++) acc[i][j] = 0.f;

    int kb0 = ks * KCH;
    for (int kt = 0; kt < KCH; kt += GBK) {
        int kb = kb0 + kt;
#pragma unroll
        for (int l = 0; l < 2; l++) {
            int lin = t + l * 256;
            int r = lin >> 2, kq = (lin & 3) << 2;
            float4 v = *(const float4*)(Ab + (size_t)r * DATA + kb + kq);
            As[r][kq + 0] = v.x; As[r][kq + 1] = v.y;
            As[r][kq + 2] = v.z; As[r][kq + 3] = v.w;
        }
#pragma unroll
        for (int l = 0; l < 2; l++) {
            int lin = t + l * 256;
            int kr = lin >> 5, n4 = (lin & 31) << 2;
            *(float4*)(&Bs[kr][n4]) = *(const float4*)(g_Wg + (size_t)(kb + kr) * DM + n4);
        }
        __syncthreads();
#pragma unroll
        for (int kk = 0; kk < GBK; kk++) {
            float a[8], b[8];
#pragma unroll
            for (int i = 0; i < 8; i++) a[i] = As[ty * 8 + i][kk];
            float4 b0 = *(const float4*)(&Bs[kk][tx * 8]);
            float4 b1 = *(const float4*)(&Bs[kk][tx * 8 + 4]);
            b[0] = b0.x; b[1] = b0.y; b[2] = b0.z; b[3] = b0.w;
            b[4] = b1.x; b[5] = b1.y; b[6] = b1.z; b[7] = b1.w;
#pragma unroll
            for (int i = 0; i < 8; i++)
#pragma unroll
                for (int j = 0; j < 8; j++)
                    acc[i][j] = fmaf(a[i], b[j], acc[i][j]);
        }
        __syncthreads();
    }
#pragma unroll
    for (int i = 0; i < 8; i++) {
        int r = r0 + ty * 8 + i;
#pragma unroll
        for (int j = 0; j < 8; j++)
            g_part[((size_t)ks * NROWS + r) * DM + tx * 8 + j] = acc[i][j];
    }
}

// ---------------- epilogue: reduce split-K, apply LN affine + bias + nan0 ------
__global__ void __launch_bounds__(128) k_epi(const float* __restrict__ redb) {
    int r = blockIdx.x, m = threadIdx.x;
    float s = 0.f;
#pragma unroll 8
    for (int ks = 0; ks < KSPL; ks++)
        s += g_part[((size_t)ks * NROWS + r) * DM + m];
    float v = g_rstd[r] * (s - g_mu[r] * g_C1[m]) + g_C2[m] + redb[m];
    if (isnan(v)) v = 0.f;
    g_exy[(size_t)r * DM + m] = v;
}

// ---------------- stage 0: global mean ----------------
__global__ void __launch_bounds__(512) k_meanz() {
    __shared__ float red[512];
    int t = threadIdx.x, m = t & 127, g = t >> 7;
    float s = 0.f;
    for (int r = g; r < NROWS; r += 4) s += g_exy[(size_t)r * DM + m];
    red[t] = s; __syncthreads();
    if (g == 0)
        g_zA[m] = (red[m] + red[m + 128] + red[m + 256] + red[m + 384]) * (1.f / NROWS);
}

// ---------------- Gram: M = (A*w) B^T, G = A B^T ----------------
__global__ void __launch_bounds__(1024) k_gram(const float* __restrict__ A,
                                               const float* __restrict__ B,
                                               const float* __restrict__ w,
                                               float* __restrict__ Mo,
                                               float* __restrict__ Go, int trans) {
    __shared__ float As[32][129], Bs[32][129], ws[DM];
    int tx = threadIdx.x, ty = threadIdx.y;
    int tid = ty * 32 + tx;
    int j0 = blockIdx.y * 32, n0 = blockIdx.x * 32;
    if (tid < DM) ws[tid] = w[tid];
    int r = tid >> 5, c4 = (tid & 31) << 2;
    float4 va = *(const float4*)(A + (size_t)(j0 + r) * DM + c4);
    As[r][c4] = va.x; As[r][c4 + 1] = va.y; As[r][c4 + 2] = va.z; As[r][c4 + 3] = va.w;
    float4 vb = *(const float4*)(B + (size_t)(n0 + r) * DM + c4);
    Bs[r][c4] = vb.x; Bs[r][c4 + 1] = vb.y; Bs[r][c4 + 2] = vb.z; Bs[r][c4 + 3] = vb.w;
    __syncthreads();
    float m = 0.f, g = 0.f;
#pragma unroll 8
    for (int d = 0; d < DM; d++) {
        float av = As[ty][d], bv = Bs[tx][d];
        m = fmaf(av * ws[d], bv, m);
        g = fmaf(av, bv, g);
    }
    int jj = j0 + ty, nn = n0 + tx;
    if (trans) { Mo[(size_t)nn * NXY + jj] = m; Go[(size_t)nn * NXY + jj] = g; }
    else       { Mo[(size_t)jj * NXY + nn] = m; Go[(size_t)jj * NXY + nn] = g; }
}

// ---------------- self-pair softmax: max pass ----------------
__global__ void __launch_bounds__(128) k_selfmax(const float* __restrict__ M,
                                                 const float* __restrict__ G,
                                                 int slot) {
    int j = blockIdx.x, t = threadIdx.x;
    float mv = -3.4e38f;
    for (int k = t; k < NXY; k += 128) {
        if (k == j) continue;
        float s = (G[(size_t)j * NXY + k] < 0.f) ? 0.f : M[(size_t)j * NXY + k];
        mv = fmaxf(mv, s);
    }
    __shared__ float red[128];
    red[t] = mv; __syncthreads();
    for (int off = 64; off; off >>= 1) {
        if (t < off) red[t] = fmaxf(red[t], red[t + off]);
        __syncthreads();
    }
    if (t == 0) atomicMax(&g_mxbits[slot], fOrd(red[0]));
}

// ---------------- self-pair softmax: exp-sum per row ----------------
__global__ void __launch_bounds__(128) k_selfsum(const float* __restrict__ M,
                                                 const float* __restrict__ G,
                                                 int slot, float* __restrict__ arow) {
    int j = blockIdx.x, t = threadIdx.x;
    float mx = fUnord(g_mxbits[slot]);
    float s = 0.f;
    for (int k = t; k < NXY; k += 128) {
        if (k == j) continue;
        float sc = (G[(size_t)j * NXY + k] < 0.f) ? 0.f : M[(size_t)j * NXY + k];
        s += expf(sc - mx);
    }
    __shared__ float red[128];
    red[t] = s; __syncthreads();
    for (int off = 64; off; off >>= 1) {
        if (t < off) red[t] += red[t + off];
        __syncthreads();
    }
    if (t == 0) arow[j] = red[0];
}

// ---------------- self stage mix: r = coef@E + zin; zout = ffn(r) ----------------
__global__ void __launch_bounds__(384) k_mix_self(const float* __restrict__ arow,
                                                  const float* __restrict__ E,
                                                  const float* __restrict__ zin,
                                                  float* __restrict__ zout,
                                                  const float* __restrict__ fW,
                                                  const float* __restrict__ fb) {
    __shared__ float red[NXY], rsh[DM];
    __shared__ float scale;
    int t = threadIdx.x;
    red[t] = arow[t]; __syncthreads();
    if (t < 128) red[t] += red[t + 128] + red[t + 256];
    __syncthreads();
    for (int off = 64; off; off >>= 1) {
        if (t < off) red[t] += red[t + off];
        __syncthreads();
    }
    if (t == 0) scale = 2.f / red[0];
    __syncthreads();
    if (t < DM) {
        float p = 0.f;
#pragma unroll 4
        for (int j = 0; j < NXY; j++) p = fmaf(arow[j], E[(size_t)j * DM + t], p);
        rsh[t] = p * scale + zin[t];
    }
    __syncthreads();
    if (t < DM) {
        float a = fb[t];
#pragma unroll 4
        for (int d = 0; d < DM; d++) a = fmaf(fW[(size_t)t * DM + d], rsh[d], a);
        zout[t] = a + rsh[t];
    }
}

// ---------------- cross stage: top-2 per column -> UB max ----------------
__global__ void __launch_bounds__(128) k_top2() {
    int n = blockIdx.x, t = threadIdx.x;
    float t1 = -3.4e38f, t2 = -3.4e38f;
    for (int j = t; j < NXY; j += 128) {
        float v = g_Gwt[(size_t)n * NXY + j];
        if (v > t1) { t2 = t1; t1 = v; } else if (v > t2) t2 = v;
    }
    __shared__ float s1[128], s2[128];
    s1[t] = t1; s2[t] = t2; __syncthreads();
    for (int off = 64; off; off >>= 1) {
        if (t < off) {
            float a1 = s1[t], a2 = s2[t], b1 = s1[t + off], b2 = s2[t + off];
            float m1 = fmaxf(a1, b1);
            float m2 = fmaxf(fminf(a1, b1), fmaxf(a2, b2));
            s1[t] = m1; s2[t] = m2;
        }
        __syncthreads();
    }
    if (t == 0) atomicMax(&g_mxbits[1], fOrd(s1[0] + s2[0]));
}

// ---------------- cross stage: per-column O(N^2) pass ----------------
__global__ void __launch_bounds__(384) k_cross() {
    __shared__ float gc[NXY], ec[NXY], red[NXY];
    int n = blockIdx.x, t = threadIdx.x;
    float mx2 = fUnord(g_mxbits[1]);
    float c0 = expf(-mx2);
    gc[t] = g_Gt[(size_t)n * NXY + t];
    ec[t] = expf(g_Gwt[(size_t)n * NXY + t] - 0.5f * mx2);
    __syncthreads();
    float gj = gc[t], ej = ec[t], thr = -gj;
    float se = 0.f;
    int cnt = 0;
#pragma unroll 4
    for (int k = 0; k < NXY; k++) {
        float gk = gc[k];
        bool msk = gk < thr;
        se += msk ? 0.f : ec[k];
        cnt += msk ? 1 : 0;
    }
    if (gj < thr) cnt--; else se -= ej;   // remove k == j
    float perj = ej * se + c0 * (float)cnt;
    g_Apart[(size_t)n * NXY + t] = perj;
    red[t] = perj; __syncthreads();
    if (t < 128) red[t] += red[t + 128] + red[t + 256];
    __syncthreads();
    for (int off = 64; off; off >>= 1) {
        if (t < off) red[t] += red[t + off];
        __syncthreads();
    }
    if (t == 0) g_colsum[n] = red[0];
}

// ---------------- reduce A coefficients over columns ----------------
__global__ void __launch_bounds__(128) k_reduceA() {
    int j = blockIdx.x * 128 + threadIdx.x;
    float a = 0.f;
#pragma unroll 4
    for (int n = 0; n < NXY; n++) a += g_Apart[(size_t)n * NXY + j];
    g_Araw[j] = a;
}

// ---------------- cross stage mix ----------------
__global__ void __launch_bounds__(384) k_mix2(const float* __restrict__ zin,
                                              float* __restrict__ zout,
                                              const float* __restrict__ fW,
                                              const float* __restrict__ fb) {
    __shared__ float red[NXY], rsh[DM];
    __shared__ float sA, sB;
    int t = threadIdx.x;
    red[t] = g_colsum[t]; __syncthreads();
    if (t < 128) red[t] += red[t + 128] + red[t + 256];
    __syncthreads();
    for (int off = 64; off; off >>= 1) {
        if (t < off) red[t] += red[t + off];
        __syncthreads();
    }
    if (t == 0) { sA = 2.f / red[0]; sB = 1.f / red[0]; }
    __syncthreads();
    if (t < DM) {
        float p1 = 0.f, p2 = 0.f;
#pragma unroll 4
        for (int j = 0; j < NXY; j++)
            p1 = fmaf(g_Araw[j], g_exy[(size_t)j * DM + t], p1);
#pragma unroll 4
        for (int n = 0; n < NXY; n++)
            p2 = fmaf(g_colsum[n], g_exy[(size_t)(NXY + n) * DM + t], p2);
        rsh[t] = p1 * sA + p2 * sB + zin[t];
    }
    __syncthreads();
    if (t < DM) {
        float a = fb[t];
#pragma unroll 4
        for (int d = 0; d < DM; d++) a = fmaf(fW[(size_t)t * DM + d], rsh[d], a);
        zout[t] = a + rsh[t];
    }
}

// ---------------- head: QNet ----------------
__global__ void __launch_bounds__(128) k_head(const float* __restrict__ z3,
                                              const float* __restrict__ qW1,
                                              const float* __restrict__ qb1,
                                              const float* __restrict__ qW2,
                                              const float* __restrict__ qb2,
                                              float* __restrict__ out) {
    __shared__ float zsh[DM], hsh[DM];
    int t = threadIdx.x;
    float zv = z3[t];
    if (isnan(zv)) zv = 0.f;
    zsh[t] = zv;
    out[2 + t] = zv;
    __syncthreads();
    float h = qb1[t];
#pragma unroll 4
    for (int d = 0; d < DM; d++) h = fmaf(qW1[(size_t)t * DM + d], zsh[d], h);
    hsh[t] = fmaxf(h, 0.f);
    __syncthreads();
    if (t < 2) {
        float o = qb2[t];
#pragma unroll 4
        for (int d = 0; d < DM; d++) o = fmaf(qW2[(size_t)t * DM + d], hsh[d], o);
        if (isnan(o)) o = 0.f;
        out[t] = o;
    }
}

// ---------------- launch ----------------
extern "C" void kernel_launch(void* const* d_in, const int* in_sizes, int n_in,
                              void* d_out, int out_size) {
    const float* input_x = (const float*)d_in[0];
    const float* input_y = (const float*)d_in[1];
    const float* ln_gamma = (const float*)d_in[2];
    const float* ln_beta = (const float*)d_in[3];
    const float* red_W = (const float*)d_in[4];
    const float* red_b = (const float*)d_in[5];
    const float* weight_x = (const float*)d_in[6];
    const float* weight_y = (const float*)d_in[7];
    const float* weight_xy = (const float*)d_in[8];
    const float* ffn_W = (const float*)d_in[9];
    const float* ffn_b = (const float*)d_in[10];
    const float* q_W1 = (const float*)d_in[11];
    const float* q_b1 = (const float*)d_in[12];
    const float* q_W2 = (const float*)d_in[13];
    const float* q_b2 = (const float*)d_in[14];
    float* out = (float*)d_out;

    float *pWg, *pC1 /*unused handles resolved via device symbols*/;
    (void)pWg; (void)pC1; (void)n_in; (void)in_sizes; (void)out_size;

    float *d_exy, *d_Mx, *d_Gx, *d_My, *d_Gy, *d_Gwt, *d_Gt, *d_arow, *d_zA, *d_zB;
    cudaGetSymbolAddress((void**)&d_exy, g_exy);
    cudaGetSymbolAddress((void**)&d_Mx, g_Mx);
    cudaGetSymbolAddress((void**)&d_Gx, g_Gx);
    cudaGetSymbolAddress((void**)&d_My, g_My);
    cudaGetSymbolAddress((void**)&d_Gy, g_Gy);
    cudaGetSymbolAddress((void**)&d_Gwt, g_Gwt);
    cudaGetSymbolAddress((void**)&d_Gt, g_Gt);
    cudaGetSymbolAddress((void**)&d_arow, g_arow);
    cudaGetSymbolAddress((void**)&d_zA, g_zA);
    cudaGetSymbolAddress((void**)&d_zB, g_zB);

    k_init<<<1, 32>>>();
    k_prepW<<<dim3(DATA / 32, DM / 32), dim3(32, 32)>>>(red_W, ln_gamma);
    k_c12<<<DM, 256>>>(red_W, ln_gamma, ln_beta);
    k_rowstats<<<NROWS, 256>>>(input_x, input_y);
    k_gemm<<<dim3(NROWS / GBM, 1, KSPL), 256>>>(input_x, input_y);
    k_epi<<<NROWS, 128>>>(red_b);
    k_meanz<<<1, 512>>>();

    const float* d_ex = d_exy;
    const float* d_ey = d_exy + (size_t)NXY * DM;
    k_gram<<<dim3(12, 12), dim3(32, 32)>>>(d_ex, d_ex, weight_x, d_Mx, d_Gx, 0);
    k_gram<<<dim3(12, 12), dim3(32, 32)>>>(d_ey, d_ey, weight_y, d_My, d_Gy, 0);
    k_gram<<<dim3(12, 12), dim3(32, 32)>>>(d_ex, d_ey, weight_xy, d_Gwt, d_Gt, 1);

    // stage 1: x-x pairs
    k_selfmax<<<NXY, 128>>>(d_Mx, d_Gx, 0);
    k_selfsum<<<NXY, 128>>>(d_Mx, d_Gx, 0, d_arow);
    k_mix_self<<<1, NXY>>>(d_arow, d_ex, d_zA, d_zB, ffn_W, ffn_b);

    // stage 2: cross pairs
    k_top2<<<NXY, 128>>>();
    k_cross<<<NXY, NXY>>>();
    k_reduceA<<<3, 128>>>();
    k_mix2<<<1, NXY>>>(d_zB, d_zA, ffn_W, ffn_b);

    // stage 3: y-y pairs
    k_selfmax<<<NXY, 128>>>(d_My, d_Gy, 2);
    k_selfsum<<<NXY, 128>>>(d_My, d_Gy, 2, d_arow);
    k_mix_self<<<1, NXY>>>(d_arow, d_ey, d_zA, d_zB, ffn_W, ffn_b);

    // head
    k_head<<<1, 128>>>(d_zB, q_W1, q_b1, q_W2, q_b2, out);
}

// round 3
// speedup vs baseline: 1.8838x; 1.8838x over previous
#include <cuda_runtime.h>
#include <math.h>

#define NXY   384
#define NROWS 768
#define DATA  4096
#define DM    128
#define EPS   1e-5f
#define KSPL  32
#define KCH   128   // DATA / KSPL
#define GBM   128
#define GBK   16

// ---------------- device scratch ----------------
__device__ float g_Wg[DATA * DM];          // gamma-scaled W transposed: [k][m]
__device__ float g_fWt[DM * DM];           // ffn_W transposed [d][m]
__device__ float g_qW1t[DM * DM];          // q_W1 transposed [d][m]
__device__ float g_C1[DM], g_C2[DM];
__device__ float g_mu[NROWS], g_rstd[NROWS];
__device__ float g_part[KSPL * NROWS * DM];
__device__ float g_exy[NROWS * DM];        // ex rows 0..383, ey rows 384..767
__device__ float g_Mx[NXY * NXY], g_Gx[NXY * NXY];
__device__ float g_My[NXY * NXY], g_Gy[NXY * NXY];
__device__ float g_Gwt[NXY * NXY];         // [n][j] (ex_j*wxy)·ey_n
__device__ float g_Gt[NXY * NXY];          // [n][j] ex_j·ey_n
__device__ float g_Apart[NXY * NXY];       // [j][n]
__device__ float g_colsum[NXY];
__device__ float g_Araw[NXY];
__device__ float g_arowX[NXY], g_arowY[NXY];
__device__ float g_mpart[96 * DM];         // mean partials
__device__ float g_zA[DM], g_zB[DM];
__device__ unsigned g_mxbits[3];

// monotone float<->uint ordering map (for atomicMax on floats)
__device__ __forceinline__ unsigned fOrd(float f) {
    unsigned u = __float_as_uint(f);
    return (u & 0x80000000u) ? ~u : (u | 0x80000000u);
}
__device__ __forceinline__ float fUnord(unsigned u) {
    return __uint_as_float((u & 0x80000000u) ? (u & 0x7FFFFFFFu) : ~u);
}

// ---------------- W prep: Wg[k][m] = gamma[k] * W[m][k] ----------------
__global__ void __launch_bounds__(1024) k_prepW(const float* __restrict__ W,
                                                const float* __restrict__ gamma) {
    __shared__ float tile[32][33];
    int k0 = blockIdx.x * 32, n0 = blockIdx.y * 32;
    tile[threadIdx.y][threadIdx.x] = W[(size_t)(n0 + threadIdx.y) * DATA + k0 + threadIdx.x];
    __syncthreads();
    int k = k0 + threadIdx.y, n = n0 + threadIdx.x;
    g_Wg[(size_t)k * DM + n] = gamma[k] * tile[threadIdx.x][threadIdx.y];
}

// ---------------- transpose ffn_W / q_W1, reset atomics ----------------
__global__ void __launch_bounds__(1024) k_prepT(const float* __restrict__ fW,
                                                const float* __restrict__ qW1) {
    if (blockIdx.x == 0 && blockIdx.y == 0 && blockIdx.z == 0 && threadIdx.x == 0 && threadIdx.y == 0) {
        g_mxbits[0] = fOrd(-3.4e38f);
        g_mxbits[1] = fOrd(0.0f);     // cross-stage UB clamp at 0 (masked score = 0)
        g_mxbits[2] = fOrd(-3.4e38f);
    }
    __shared__ float tile[32][33];
    const float* src = blockIdx.z ? qW1 : fW;
    float* dst = blockIdx.z ? g_qW1t : g_fWt;
    int c0 = blockIdx.x * 32, r0 = blockIdx.y * 32;
    tile[threadIdx.y][threadIdx.x] = src[(size_t)(r0 + threadIdx.y) * DM + c0 + threadIdx.x];
    __syncthreads();
    dst[(size_t)(c0 + threadIdx.y) * DM + r0 + threadIdx.x] = tile[threadIdx.x][threadIdx.y];
}

// ---------------- C1[m] = sum gamma*W[m], C2[m] = sum beta*W[m] ----------------
__global__ void __launch_bounds__(256) k_c12(const float* __restrict__ W,
                                             const float* __restrict__ gamma,
                                             const float* __restrict__ beta) {
    int m = blockIdx.x, t = threadIdx.x;
    float c1 = 0.f, c2 = 0.f;
    for (int d = t; d < DATA; d += 256) {
        float wv = W[(size_t)m * DATA + d];
        c1 += gamma[d] * wv;
        c2 += beta[d] * wv;
    }
    __shared__ float r1[256], r2[256];
    r1[t] = c1; r2[t] = c2; __syncthreads();
    for (int off = 128; off; off >>= 1) {
        if (t < off) { r1[t] += r1[t + off]; r2[t] += r2[t + off]; }
        __syncthreads();
    }
    if (t == 0) { g_C1[m] = r1[0]; g_C2[m] = r2[0]; }
}

// ---------------- per-row mean / rstd (512 thr, 2x float4 each) ----------------
__global__ void __launch_bounds__(512) k_rowstats(const float* __restrict__ x,
                                                  const float* __restrict__ y) {
    int r = blockIdx.x, t = threadIdx.x;
    const float* p = (r < NXY) ? (x + (size_t)r * DATA) : (y + (size_t)(r - NXY) * DATA);
    float4 v0 = *(const float4*)(p + t * 8);
    float4 v1 = *(const float4*)(p + t * 8 + 4);
    float s = v0.x + v0.y + v0.z + v0.w + v1.x + v1.y + v1.z + v1.w;
    float q = v0.x*v0.x + v0.y*v0.y + v0.z*v0.z + v0.w*v0.w
            + v1.x*v1.x + v1.y*v1.y + v1.z*v1.z + v1.w*v1.w;
#pragma unroll
    for (int o = 16; o; o >>= 1) {
        s += __shfl_xor_sync(0xffffffffu, s, o);
        q += __shfl_xor_sync(0xffffffffu, q, o);
    }
    __shared__ float ws[16], wq[16];
    int wid = t >> 5, lane = t & 31;
    if (lane == 0) { ws[wid] = s; wq[wid] = q; }
    __syncthreads();
    if (t == 0) {
        float ss = 0.f, qq = 0.f;
#pragma unroll
        for (int i = 0; i < 16; i++) { ss += ws[i]; qq += wq[i]; }
        float mu = ss * (1.f / DATA);
        float var = qq * (1.f / DATA) - mu * mu;
        g_mu[r] = mu;
        g_rstd[r] = rsqrtf(var + EPS);
    }
}

// ---------------- main GEMM: [768 x 4096] @ Wg[4096 x 128], split-K ----------------
__global__ void __launch_bounds__(256) k_gemm(const float* __restrict__ x,
                                              const float* __restrict__ y) {
    __shared__ float As[GBM][GBK + 1];
    __shared__ float Bs[GBK][DM];
    int t = threadIdx.x, tx = t & 15, ty = t >> 4;
    int r0 = blockIdx.x * GBM;
    int ks = blockIdx.z;
    const float* Ab = (r0 < NXY) ? (x + (size_t)r0 * DATA)
                                 : (y + (size_t)(r0 - NXY) * DATA);
    float acc[8][8];
#pragma unroll
    for (int i = 0; i < 8; i++)
#pragma unroll
        for (int j = 0; j < 8; j++) acc[i][j] = 0.f;

    int kb0 = ks * KCH;
    for (int kt = 0; kt < KCH; kt += GBK) {
        int kb = kb0 + kt;
#pragma unroll
        for (int l = 0; l < 2; l++) {
            int lin = t + l * 256;
            int r = lin >> 2, kq = (lin & 3) << 2;
            float4 v = *(const float4*)(Ab + (size_t)r * DATA + kb + kq);
            As[r][kq + 0] = v.x; As[r][kq + 1] = v.y;
            As[r][kq + 2] = v.z; As[r][kq + 3] = v.w;
        }
#pragma unroll
        for (int l = 0; l < 2; l++) {
            int lin = t + l * 256;
            int kr = lin >> 5, n4 = (lin & 31) << 2;
            *(float4*)(&Bs[kr][n4]) = *(const float4*)(g_Wg + (size_t)(kb + kr) * DM + n4);
        }
        __syncthreads();
#pragma unroll
        for (int kk = 0; kk < GBK; kk++) {
            float a[8], b[8];
#pragma unroll
            for (int i = 0; i < 8; i++) a[i] = As[ty * 8 + i][kk];
            float4 b0 = *(const float4*)(&Bs[kk][tx * 8]);
            float4 b1 = *(const float4*)(&Bs[kk][tx * 8 + 4]);
            b[0] = b0.x; b[1] = b0.y; b[2] = b0.z; b[3] = b0.w;
            b[4] = b1.x; b[5] = b1.y; b[6] = b1.z; b[7] = b1.w;
#pragma unroll
            for (int i = 0; i < 8; i++)
#pragma unroll
                for (int j = 0; j < 8; j++)
                    acc[i][j] = fmaf(a[i], b[j], acc[i][j]);
        }
        __syncthreads();
    }
#pragma unroll
    for (int i = 0; i < 8; i++) {
        int r = r0 + ty * 8 + i;
#pragma unroll
        for (int j = 0; j < 8; j++)
            g_part[((size_t)ks * NROWS + r) * DM + tx * 8 + j] = acc[i][j];
    }
}

// ---------------- epilogue: reduce split-K, apply LN affine + bias + nan0 ------
__global__ void __launch_bounds__(128) k_epi(const float* __restrict__ redb) {
    int r = blockIdx.x, m = threadIdx.x;
    float s = 0.f;
#pragma unroll 8
    for (int ks = 0; ks < KSPL; ks++)
        s += g_part[((size_t)ks * NROWS + r) * DM + m];
    float v = g_rstd[r] * (s - g_mu[r] * g_C1[m]) + g_C2[m] + redb[m];
    if (isnan(v)) v = 0.f;
    g_exy[(size_t)r * DM + m] = v;
}

// ---------------- stage 0: global-mean partials (96 blocks x 8 rows) ----------
__global__ void __launch_bounds__(128) k_meanz() {
    int b = blockIdx.x, m = threadIdx.x;
    float s = 0.f;
#pragma unroll
    for (int r = 0; r < 8; r++)
        s += g_exy[(size_t)(b * 8 + r) * DM + m];
    g_mpart[(size_t)b * DM + m] = s;
}

// ---------------- Gram: M = (A*w) B^T, G = A B^T (+ fused masked max) --------
__global__ void __launch_bounds__(1024) k_gram(const float* __restrict__ A,
                                               const float* __restrict__ B,
                                               const float* __restrict__ w,
                                               float* __restrict__ Mo,
                                               float* __restrict__ Go,
                                               int trans, int slot) {
    __shared__ float As[32][129], Bs[32][129], ws[DM];
    int tx = threadIdx.x, ty = threadIdx.y;
    int tid = ty * 32 + tx;
    int j0 = blockIdx.y * 32, n0 = blockIdx.x * 32;
    if (tid < DM) ws[tid] = w[tid];
    int r = tid >> 5, c4 = (tid & 31) << 2;
    float4 va = *(const float4*)(A + (size_t)(j0 + r) * DM + c4);
    As[r][c4] = va.x; As[r][c4 + 1] = va.y; As[r][c4 + 2] = va.z; As[r][c4 + 3] = va.w;
    float4 vb = *(const float4*)(B + (size_t)(n0 + r) * DM + c4);
    Bs[r][c4] = vb.x; Bs[r][c4 + 1] = vb.y; Bs[r][c4 + 2] = vb.z; Bs[r][c4 + 3] = vb.w;
    __syncthreads();
    float m = 0.f, g = 0.f;
#pragma unroll 8
    for (int d = 0; d < DM; d++) {
        float av = As[ty][d], bv = Bs[tx][d];
        m = fmaf(av * ws[d], bv, m);
        g = fmaf(av, bv, g);
    }
    int jj = j0 + ty, nn = n0 + tx;
    if (trans) { Mo[(size_t)nn * NXY + jj] = m; Go[(size_t)nn * NXY + jj] = g; }
    else       { Mo[(size_t)jj * NXY + nn] = m; Go[(size_t)jj * NXY + nn] = g; }
    if (slot >= 0) {
        // masked self-pair score for the global softmax max (exclude diagonal)
        float sc = (g < 0.f) ? 0.f : m;
        if (jj == nn) sc = -3.4e38f;
#pragma unroll
        for (int o = 16; o; o >>= 1)
            sc = fmaxf(sc, __shfl_xor_sync(0xffffffffu, sc, o));
        __shared__ float wmax[32];
        int wid = tid >> 5, lane = tid & 31;
        if (lane == 0) wmax[wid] = sc;
        __syncthreads();
        if (tid == 0) {
            float mx = wmax[0];
#pragma unroll
            for (int i = 1; i < 32; i++) mx = fmaxf(mx, wmax[i]);
            atomicMax(&g_mxbits[slot], fOrd(mx));
        }
    }
}

// ---------------- self-pair softmax: exp-sum per row ----------------
__global__ void __launch_bounds__(128) k_selfsum(const float* __restrict__ M,
                                                 const float* __restrict__ G,
                                                 int slot, float* __restrict__ arow) {
    int j = blockIdx.x, t = threadIdx.x;
    float mx = fUnord(g_mxbits[slot]);
    float s = 0.f;
    for (int k = t; k < NXY; k += 128) {
        if (k == j) continue;
        float sc = (G[(size_t)j * NXY + k] < 0.f) ? 0.f : M[(size_t)j * NXY + k];
        s += expf(sc - mx);
    }
    __shared__ float red[128];
    red[t] = s; __syncthreads();
    for (int off = 64; off; off >>= 1) {
        if (t < off) red[t] += red[t + off];
        __syncthreads();
    }
    if (t == 0) arow[j] = red[0];
}

// ---------------- self stage mix: r = coef@E + zin; zout = ffn(r)+r ----------
__global__ void __launch_bounds__(512) k_mix_self(const float* __restrict__ arow,
                                                  const float* __restrict__ E,
                                                  const float* __restrict__ zin,
                                                  float* __restrict__ zout,
                                                  const float* __restrict__ fb,
                                                  int useMean) {
    __shared__ float ash[NXY], part[4][DM], part2[4][DM], rsh[DM];
    __shared__ float sscale, wsum[16];
    int t = threadIdx.x, m = t & 127, g = t >> 7;
    int wid = t >> 5, lane = t & 31;
    float av = (t < NXY) ? arow[t] : 0.f;
    if (t < NXY) ash[t] = av;
#pragma unroll
    for (int o = 16; o; o >>= 1) av += __shfl_xor_sync(0xffffffffu, av, o);
    if (lane == 0) wsum[wid] = av;
    __syncthreads();
    if (t == 0) {
        float s = 0.f;
#pragma unroll
        for (int i = 0; i < 16; i++) s += wsum[i];
        sscale = 2.f / s;
    }
    // pairwise-mix matvec, j-slice per group
    {
        float p = 0.f;
        int j0 = g * 96;
#pragma unroll 8
        for (int j = j0; j < j0 + 96; j++)
            p = fmaf(ash[j], E[(size_t)j * DM + m], p);
        part[g][m] = p;
    }
    // mean partials (stage 1 only)
    if (useMean) {
        float p = 0.f;
        int b0 = g * 24;
#pragma unroll 8
        for (int b = b0; b < b0 + 24; b++)
            p += g_mpart[(size_t)b * DM + m];
        part2[g][m] = p;
    }
    __syncthreads();
    if (g == 0) {
        float p = part[0][m] + part[1][m] + part[2][m] + part[3][m];
        float z = useMean
            ? (part2[0][m] + part2[1][m] + part2[2][m] + part2[3][m]) * (1.f / NROWS)
            : zin[m];
        rsh[m] = p * sscale + z;
    }
    __syncthreads();
    // ffn: a[m] = sum_d fWt[d][m] * r[d], d-slice per group
    {
        float a = 0.f;
        int d0 = g * 32;
#pragma unroll 8
        for (int d = d0; d < d0 + 32; d++)
            a = fmaf(g_fWt[(size_t)d * DM + m], rsh[d], a);
        part[g][m] = a;
    }
    __syncthreads();
    if (g == 0)
        zout[m] = part[0][m] + part[1][m] + part[2][m] + part[3][m] + fb[m] + rsh[m];
}

// ---------------- cross stage: top-2 per column -> UB max ----------------
__global__ void __launch_bounds__(128) k_top2() {
    int n = blockIdx.x, t = threadIdx.x;
    float t1 = -3.4e38f, t2 = -3.4e38f;
    for (int j = t; j < NXY; j += 128) {
        float v = g_Gwt[(size_t)n * NXY + j];
        if (v > t1) { t2 = t1; t1 = v; } else if (v > t2) t2 = v;
    }
    __shared__ float s1[128], s2[128];
    s1[t] = t1; s2[t] = t2; __syncthreads();
    for (int off = 64; off; off >>= 1) {
        if (t < off) {
            float a1 = s1[t], a2 = s2[t], b1 = s1[t + off], b2 = s2[t + off];
            float m1 = fmaxf(a1, b1);
            float m2 = fmaxf(fminf(a1, b1), fmaxf(a2, b2));
            s1[t] = m1; s2[t] = m2;
        }
        __syncthreads();
    }
    if (t == 0) atomicMax(&g_mxbits[1], fOrd(s1[0] + s2[0]));
}

// ---------------- cross stage: per-column O(N^2) pass ----------------
__global__ void __launch_bounds__(384) k_cross() {
    __shared__ float gc[NXY], ec[NXY], red[NXY];
    int n = blockIdx.x, t = threadIdx.x;
    float mx2 = fUnord(g_mxbits[1]);
    float c0 = expf(-mx2);
    gc[t] = g_Gt[(size_t)n * NXY + t];
    ec[t] = expf(g_Gwt[(size_t)n * NXY + t] - 0.5f * mx2);
    __syncthreads();
    float gj = gc[t], ej = ec[t], thr = -gj;
    float se = 0.f;
    int cnt = 0;
#pragma unroll 4
    for (int k = 0; k < NXY; k++) {
        float gk = gc[k];
        bool msk = gk < thr;
        se += msk ? 0.f : ec[k];
        cnt += msk ? 1 : 0;
    }
    if (gj < thr) cnt--; else se -= ej;   // remove k == j
    float perj = ej * se + c0 * (float)cnt;
    g_Apart[(size_t)t * NXY + n] = perj;  // transposed store -> coalesced reduce
    red[t] = perj; __syncthreads();
    if (t < 128) red[t] += red[t + 128] + red[t + 256];
    __syncthreads();
    for (int off = 64; off; off >>= 1) {
        if (t < off) red[t] += red[t + off];
        __syncthreads();
    }
    if (t == 0) g_colsum[n] = red[0];
}

// ---------------- reduce A coefficients (coalesced rows) ----------------
__global__ void __launch_bounds__(128) k_reduceA() {
    int j = blockIdx.x, t = threadIdx.x;
    const float* row = g_Apart + (size_t)j * NXY;
    float s = row[t] + row[t + 128] + row[t + 256];
#pragma unroll
    for (int o = 16; o; o >>= 1) s += __shfl_xor_sync(0xffffffffu, s, o);
    __shared__ float ws[4];
    if ((t & 31) == 0) ws[t >> 5] = s;
    __syncthreads();
    if (t == 0) g_Araw[j] = ws[0] + ws[1] + ws[2] + ws[3];
}

// ---------------- cross stage mix ----------------
__global__ void __launch_bounds__(512) k_mix2(const float* __restrict__ zin,
                                              float* __restrict__ zout,
                                              const float* __restrict__ fb) {
    __shared__ float csh[NROWS], part[4][DM], rsh[DM];
    __shared__ float sA, sB, wsum[16];
    int t = threadIdx.x, m = t & 127, g = t >> 7;
    int wid = t >> 5, lane = t & 31;
    float cv = (t < NXY) ? g_colsum[t] : 0.f;
#pragma unroll
    for (int o = 16; o; o >>= 1) cv += __shfl_xor_sync(0xffffffffu, cv, o);
    if (lane == 0) wsum[wid] = cv;
    __syncthreads();
    if (t == 0) {
        float s = 0.f;
#pragma unroll
        for (int i = 0; i < 16; i++) s += wsum[i];
        sA = 2.f / s; sB = 1.f / s;
    }
    __syncthreads();
    if (t < NXY) {
        csh[t] = g_Araw[t] * sA;
        csh[NXY + t] = g_colsum[t] * sB;
    }
    __syncthreads();
    {
        float p = 0.f;
        int j0 = g * 192;
#pragma unroll 8
        for (int j = j0; j < j0 + 192; j++)
            p = fmaf(csh[j], g_exy[(size_t)j * DM + m], p);
        part[g][m] = p;
    }
    __syncthreads();
    if (g == 0)
        rsh[m] = part[0][m] + part[1][m] + part[2][m] + part[3][m] + zin[m];
    __syncthreads();
    {
        float a = 0.f;
        int d0 = g * 32;
#pragma unroll 8
        for (int d = d0; d < d0 + 32; d++)
            a = fmaf(g_fWt[(size_t)d * DM + m], rsh[d], a);
        part[g][m] = a;
    }
    __syncthreads();
    if (g == 0)
        zout[m] = part[0][m] + part[1][m] + part[2][m] + part[3][m] + fb[m] + rsh[m];
}

// ---------------- head: QNet ----------------
__global__ void __launch_bounds__(512) k_head(const float* __restrict__ z3,
                                              const float* __restrict__ qb1,
                                              const float* __restrict__ qW2,
                                              const float* __restrict__ qb2,
                                              float* __restrict__ out) {
    __shared__ float zsh[DM], hsh[DM], part[4][DM];
    int t = threadIdx.x, m = t & 127, g = t >> 7;
    if (g == 0) {
        float zv = z3[m];
        if (isnan(zv)) zv = 0.f;
        zsh[m] = zv;
        out[2 + m] = zv;
    }
    __syncthreads();
    {
        float a = 0.f;
        int d0 = g * 32;
#pragma unroll 8
        for (int d = d0; d < d0 + 32; d++)
            a = fmaf(g_qW1t[(size_t)d * DM + m], zsh[d], a);
        part[g][m] = a;
    }
    __syncthreads();
    if (g == 0)
        hsh[m] = fmaxf(part[0][m] + part[1][m] + part[2][m] + part[3][m] + qb1[m], 0.f);
    __syncthreads();
    if (t < 64) {
        int o = t >> 5, lane = t & 31;
        float s = 0.f;
#pragma unroll
        for (int d = lane; d < DM; d += 32)
            s = fmaf(qW2[(size_t)o * DM + d], hsh[d], s);
#pragma unroll
        for (int off = 16; off; off >>= 1) s += __shfl_xor_sync(0xffffffffu, s, off);
        if (lane == 0) {
            float v = s + qb2[o];
            if (isnan(v)) v = 0.f;
            out[o] = v;
        }
    }
}

// ---------------- launch ----------------
extern "C" void kernel_launch(void* const* d_in, const int* in_sizes, int n_in,
                              void* d_out, int out_size) {
    const float* input_x = (const float*)d_in[0];
    const float* input_y = (const float*)d_in[1];
    const float* ln_gamma = (const float*)d_in[2];
    const float* ln_beta = (const float*)d_in[3];
    const float* red_W = (const float*)d_in[4];
    const float* red_b = (const float*)d_in[5];
    const float* weight_x = (const float*)d_in[6];
    const float* weight_y = (const float*)d_in[7];
    const float* weight_xy = (const float*)d_in[8];
    const float* ffn_W = (const float*)d_in[9];
    const float* ffn_b = (const float*)d_in[10];
    const float* q_W1 = (const float*)d_in[11];
    const float* q_b1 = (const float*)d_in[12];
    const float* q_W2 = (const float*)d_in[13];
    const float* q_b2 = (const float*)d_in[14];
    float* out = (float*)d_out;
    (void)n_in; (void)in_sizes; (void)out_size;

    float *d_exy, *d_Mx, *d_Gx, *d_My, *d_Gy, *d_Gwt, *d_Gt, *d_arowX, *d_arowY, *d_zA, *d_zB;
    cudaGetSymbolAddress((void**)&d_exy, g_exy);
    cudaGetSymbolAddress((void**)&d_Mx, g_Mx);
    cudaGetSymbolAddress((void**)&d_Gx, g_Gx);
    cudaGetSymbolAddress((void**)&d_My, g_My);
    cudaGetSymbolAddress((void**)&d_Gy, g_Gy);
    cudaGetSymbolAddress((void**)&d_Gwt, g_Gwt);
    cudaGetSymbolAddress((void**)&d_Gt, g_Gt);
    cudaGetSymbolAddress((void**)&d_arowX, g_arowX);
    cudaGetSymbolAddress((void**)&d_arowY, g_arowY);
    cudaGetSymbolAddress((void**)&d_zA, g_zA);
    cudaGetSymbolAddress((void**)&d_zB, g_zB);

    k_prepW<<<dim3(DATA / 32, DM / 32), dim3(32, 32)>>>(red_W, ln_gamma);
    k_prepT<<<dim3(4, 4, 2), dim3(32, 32)>>>(ffn_W, q_W1);
    k_c12<<<DM, 256>>>(red_W, ln_gamma, ln_beta);
    k_rowstats<<<NROWS, 512>>>(input_x, input_y);
    k_gemm<<<dim3(NROWS / GBM, 1, KSPL), 256>>>(input_x, input_y);
    k_epi<<<NROWS, 128>>>(red_b);
    k_meanz<<<96, 128>>>();

    const float* d_ex = d_exy;
    const float* d_ey = d_exy + (size_t)NXY * DM;
    k_gram<<<dim3(12, 12), dim3(32, 32)>>>(d_ex, d_ex, weight_x, d_Mx, d_Gx, 0, 0);
    k_gram<<<dim3(12, 12), dim3(32, 32)>>>(d_ey, d_ey, weight_y, d_My, d_Gy, 0, 2);
    k_gram<<<dim3(12, 12), dim3(32, 32)>>>(d_ex, d_ey, weight_xy, d_Gwt, d_Gt, 1, -1);

    // independent score reductions (before the serial mix tail)
    k_selfsum<<<NXY, 128>>>(d_Mx, d_Gx, 0, d_arowX);
    k_selfsum<<<NXY, 128>>>(d_My, d_Gy, 2, d_arowY);
    k_top2<<<NXY, 128>>>();
    k_cross<<<NXY, NXY>>>();
    k_reduceA<<<NXY, 128>>>();

    // serial mix tail
    k_mix_self<<<1, 512>>>(d_arowX, d_ex, d_zA, d_zB, ffn_b, 1);
    k_mix2<<<1, 512>>>(d_zB, d_zA, ffn_b);
    k_mix_self<<<1, 512>>>(d_arowY, d_ey, d_zA, d_zB, ffn_b, 0);
    k_head<<<1, 512>>>(d_zB, q_b1, q_W2, q_b2, out);
}